// round 2
// baseline (speedup 1.0000x reference)
#include <cuda_runtime.h>
#include <math.h>

#define NB    32
#define EDIM  256
#define NHEAD 8
#define KDIM  16
#define VDIM  64
#define DHD   512
#define HQ    768
#define NPIX  400
#define SPIX  196
#define PADV  66

typedef unsigned long long ull;

__device__ __forceinline__ ull fma2(ull a, ull b, ull c) {
    ull d;
    asm("fma.rn.f32x2 %0, %1, %2, %3;" : "=l"(d) : "l"(a), "l"(b), "l"(c));
    return d;
}
__device__ __forceinline__ float f2lo(ull v) { return __uint_as_float((unsigned)v); }
__device__ __forceinline__ float f2hi(ull v) { return __uint_as_float((unsigned)(v >> 32)); }

// ---------------- device scratch ----------------
__device__ float g_qkv [NB*HQ*NPIX];
__device__ float g_qdw [NB*128*NPIX];
__device__ float g_tmpb[NHEAD*NPIX*SPIX];
__device__ float g_bias[NHEAD*NPIX*NPIX];
__device__ float g_ot  [NB*NPIX*DHD];
__device__ float g_y1  [NB*EDIM*NPIX];
__device__ float g_hb  [NB*DHD*NPIX];
__device__ int   g_midx[NPIX*4];
__device__ float g_mw  [NPIX*4];

// ---------------- bicubic taps ----------------
__global__ void k_mtaps() {
    int i = blockIdx.x*blockDim.x + threadIdx.x;
    if (i >= NPIX) return;
    double scale = (double)SPIX / (double)NPIX;
    double src = (i + 0.5)*scale - 0.5;
    double f = floor(src);
    double t = src - f;
    const double a = -0.75;
    for (int j = -1; j <= 2; j++) {
        double xx = fabs((double)j - t);
        double w;
        if (xx <= 1.0)      w = (a+2.0)*xx*xx*xx - (a+3.0)*xx*xx + 1.0;
        else if (xx < 2.0)  w = a*xx*xx*xx - 5.0*a*xx*xx + 8.0*a*xx - 4.0*a;
        else                w = 0.0;
        int idx = (int)f + j;
        idx = min(max(idx, 0), SPIX-1);
        g_midx[i*4 + (j+1)] = idx;
        g_mw  [i*4 + (j+1)] = (float)w;
    }
}

__global__ void k_bias1(const float* __restrict__ ab, const int* __restrict__ idxs) {
    int i = blockIdx.x*blockDim.x + threadIdx.x;
    if (i >= NHEAD*NPIX*SPIX) return;
    int t = i % SPIX;
    int n = (i / SPIX) % NPIX;
    int h = i / (SPIX*NPIX);
    float acc = 0.f;
    #pragma unroll
    for (int k = 0; k < 4; k++) {
        int s = g_midx[n*4+k];
        acc += g_mw[n*4+k] * ab[h*SPIX + idxs[s*SPIX + t]];
    }
    g_tmpb[i] = acc;
}

__global__ void k_bias2() {
    int i = blockIdx.x*blockDim.x + threadIdx.x;
    if (i >= NHEAD*NPIX*NPIX) return;
    int m = i % NPIX;
    int n = (i / NPIX) % NPIX;
    int h = i / (NPIX*NPIX);
    const float* trow = g_tmpb + ((size_t)h*NPIX + n)*SPIX;
    float acc = 0.f;
    #pragma unroll
    for (int k = 0; k < 4; k++)
        acc += g_mw[m*4+k] * trow[g_midx[m*4+k]];
    g_bias[i] = acc;
}

// ---------------- depthwise 3x3 ----------------
__global__ void k_dwconv(const float* __restrict__ w, const float* __restrict__ s,
                         const float* __restrict__ bia) {
    int i = blockIdx.x*blockDim.x + threadIdx.x;
    if (i >= NB*128*NPIX) return;
    int p = i % NPIX;
    int c = (i / NPIX) % 128;
    int b = i / (128*NPIX);
    int y = p / 20, x = p % 20;
    const float* src = g_qkv + ((size_t)b*HQ + c)*NPIX;
    float acc = 0.f;
    #pragma unroll
    for (int dy = -1; dy <= 1; dy++) {
        int yy = y + dy;
        if (yy < 0 || yy >= 20) continue;
        #pragma unroll
        for (int dx = -1; dx <= 1; dx++) {
            int xx = x + dx;
            if (xx < 0 || xx >= 20) continue;
            acc += w[c*9 + (dy+1)*3 + (dx+1)] * src[yy*20 + xx];
        }
    }
    g_qdw[i] = acc * s[c] + bia[c];
}

// ---------------- packed-f32x2 GEMM ----------------
// CTA tile 128(O) x 64(p), 256 threads, micro 8x4 (M-pairs packed).
// Xs2 stores each X value DUPLICATED so LDS.128 yields broadcast pairs.
// flags: bit0 reluIn, bit1 reluOut, bit2 X transposed [b][p][Cin]
__global__ void __launch_bounds__(256) k_gemm2(
    const float* __restrict__ X, const float* __restrict__ W,
    const float* __restrict__ sc, const float* __restrict__ bi,
    const float* __restrict__ R, float* __restrict__ Y,
    int O, int Cin, int flags)
{
    __shared__ float Ws [16][128];
    __shared__ float Xs2[16][128];
    const int b  = blockIdx.z;
    const int oT = blockIdx.y * 128;
    const int pT = blockIdx.x * 64;
    const int t  = threadIdx.x;
    const int ty = t >> 4, tx = t & 15;
    const bool reluIn = flags & 1;
    const bool xT     = (flags & 4) != 0;

    ull acc[4][4];
    #pragma unroll
    for (int i = 0; i < 4; i++)
        #pragma unroll
        for (int j = 0; j < 4; j++) acc[i][j] = 0ull;

    const int mW = t >> 1;
    const int kW = (t & 1) * 8;

    for (int k0 = 0; k0 < Cin; k0 += 16) {
        // --- W tile: 128 rows x 16 k ---
        {
            const float* wp = &W[(size_t)(oT + mW)*Cin + k0 + kW];
            float4 w0 = *(const float4*)(wp);
            float4 w1 = *(const float4*)(wp + 4);
            Ws[kW+0][mW] = w0.x; Ws[kW+1][mW] = w0.y;
            Ws[kW+2][mW] = w0.z; Ws[kW+3][mW] = w0.w;
            Ws[kW+4][mW] = w1.x; Ws[kW+5][mW] = w1.y;
            Ws[kW+6][mW] = w1.z; Ws[kW+7][mW] = w1.w;
        }
        // --- X tile (duplicated store) ---
        if (!xT) {
            const int kx  = t >> 4;
            const int px4 = (t & 15) * 4;
            const int p   = pT + px4;
            float4 xv = make_float4(0.f,0.f,0.f,0.f);
            if (p < NPIX)
                xv = *(const float4*)&X[((size_t)b*Cin + k0 + kx)*NPIX + p];
            if (reluIn) {
                xv.x = fmaxf(xv.x,0.f); xv.y = fmaxf(xv.y,0.f);
                xv.z = fmaxf(xv.z,0.f); xv.w = fmaxf(xv.w,0.f);
            }
            float4 d0 = make_float4(xv.x, xv.x, xv.y, xv.y);
            float4 d1 = make_float4(xv.z, xv.z, xv.w, xv.w);
            *(float4*)&Xs2[kx][2*px4]     = d0;
            *(float4*)&Xs2[kx][2*px4 + 4] = d1;
        } else {
            const int px = t >> 2;
            const int kx = (t & 3) * 4;
            const int p  = pT + px;
            float4 xv = make_float4(0.f,0.f,0.f,0.f);
            if (p < NPIX)
                xv = *(const float4*)&X[((size_t)b*NPIX + p)*Cin + k0 + kx];
            if (reluIn) {
                xv.x = fmaxf(xv.x,0.f); xv.y = fmaxf(xv.y,0.f);
                xv.z = fmaxf(xv.z,0.f); xv.w = fmaxf(xv.w,0.f);
            }
            Xs2[kx+0][2*px] = xv.x; Xs2[kx+0][2*px+1] = xv.x;
            Xs2[kx+1][2*px] = xv.y; Xs2[kx+1][2*px+1] = xv.y;
            Xs2[kx+2][2*px] = xv.z; Xs2[kx+2][2*px+1] = xv.z;
            Xs2[kx+3][2*px] = xv.w; Xs2[kx+3][2*px+1] = xv.w;
        }
        __syncthreads();
        #pragma unroll
        for (int k = 0; k < 16; k++) {
            ulonglong2 a0 = *(const ulonglong2*)&Ws [k][ty*8];
            ulonglong2 a1 = *(const ulonglong2*)&Ws [k][ty*8 + 4];
            ulonglong2 b0 = *(const ulonglong2*)&Xs2[k][tx*8];
            ulonglong2 b1 = *(const ulonglong2*)&Xs2[k][tx*8 + 4];
            acc[0][0] = fma2(a0.x, b0.x, acc[0][0]);
            acc[0][1] = fma2(a0.x, b0.y, acc[0][1]);
            acc[0][2] = fma2(a0.x, b1.x, acc[0][2]);
            acc[0][3] = fma2(a0.x, b1.y, acc[0][3]);
            acc[1][0] = fma2(a0.y, b0.x, acc[1][0]);
            acc[1][1] = fma2(a0.y, b0.y, acc[1][1]);
            acc[1][2] = fma2(a0.y, b1.x, acc[1][2]);
            acc[1][3] = fma2(a0.y, b1.y, acc[1][3]);
            acc[2][0] = fma2(a1.x, b0.x, acc[2][0]);
            acc[2][1] = fma2(a1.x, b0.y, acc[2][1]);
            acc[2][2] = fma2(a1.x, b1.x, acc[2][2]);
            acc[2][3] = fma2(a1.x, b1.y, acc[2][3]);
            acc[3][0] = fma2(a1.y, b0.x, acc[3][0]);
            acc[3][1] = fma2(a1.y, b0.y, acc[3][1]);
            acc[3][2] = fma2(a1.y, b1.x, acc[3][2]);
            acc[3][3] = fma2(a1.y, b1.y, acc[3][3]);
        }
        __syncthreads();
    }

    const bool reluOut = (flags & 2) != 0;
    const int p0 = pT + tx*4;
    if (p0 < NPIX) {
        #pragma unroll
        for (int mi = 0; mi < 4; mi++) {
            const int r0 = oT + ty*8 + 2*mi;
            const int r1 = r0 + 1;
            const float s0 = sc[r0], b0 = bi[r0];
            const float s1 = sc[r1], b1 = bi[r1];
            float4 v0, v1;
            v0.x = f2lo(acc[mi][0])*s0 + b0;
            v0.y = f2lo(acc[mi][1])*s0 + b0;
            v0.z = f2lo(acc[mi][2])*s0 + b0;
            v0.w = f2lo(acc[mi][3])*s0 + b0;
            v1.x = f2hi(acc[mi][0])*s1 + b1;
            v1.y = f2hi(acc[mi][1])*s1 + b1;
            v1.z = f2hi(acc[mi][2])*s1 + b1;
            v1.w = f2hi(acc[mi][3])*s1 + b1;
            if (reluOut) {
                v0.x=fmaxf(v0.x,0.f); v0.y=fmaxf(v0.y,0.f); v0.z=fmaxf(v0.z,0.f); v0.w=fmaxf(v0.w,0.f);
                v1.x=fmaxf(v1.x,0.f); v1.y=fmaxf(v1.y,0.f); v1.z=fmaxf(v1.z,0.f); v1.w=fmaxf(v1.w,0.f);
            }
            const size_t off0 = ((size_t)b*O + r0)*NPIX + p0;
            const size_t off1 = ((size_t)b*O + r1)*NPIX + p0;
            if (R) {
                float4 r0v = *(const float4*)&R[off0];
                float4 r1v = *(const float4*)&R[off1];
                v0.x+=r0v.x; v0.y+=r0v.y; v0.z+=r0v.z; v0.w+=r0v.w;
                v1.x+=r1v.x; v1.y+=r1v.y; v1.z+=r1v.z; v1.w+=r1v.w;
            }
            *(float4*)&Y[off0] = v0;
            *(float4*)&Y[off1] = v1;
        }
    }
}

// ---------------- fused attention ----------------
// One CTA per (b,h). K [16][400] and V [400][PADV] in smem.
// Each warp processes 2 query rows per pass (25 passes, q = pass*16 + w*2 + j).
// Probabilities stored DUPLICATED in smem so PV uses packed f32x2 FMA with
// pair operands loaded directly (no register packing MOVs).
__global__ void __launch_bounds__(256) k_attn2() {
    extern __shared__ float sm[];
    float* Ks  = sm;                        // [16][400]
    float* Vs  = Ks + KDIM*NPIX;            // [400][PADV]
    float* Ps2 = Vs + NPIX*PADV;            // [8 warps][2 rows][800]
    const int bh = blockIdx.x;
    const int b = bh >> 3, h = bh & 7;
    const int tid = threadIdx.x;

    const float* qb = g_qdw + ((size_t)b*128 + h*KDIM)*NPIX;
    const float* kb = g_qkv + ((size_t)b*HQ + 128 + h*KDIM)*NPIX;
    const float* vb = g_qkv + ((size_t)b*HQ + 256 + h*VDIM)*NPIX;

    for (int i = tid; i < KDIM*NPIX; i += 256) Ks[i] = kb[i];
    for (int i = tid; i < VDIM*NPIX; i += 256) {
        int d = i / NPIX, p = i - d*NPIX;
        Vs[p*PADV + d] = vb[i];
    }
    __syncthreads();

    const int w = tid >> 5, lane = tid & 31;
    float* Pw0 = Ps2 + (size_t)w*1600;
    float* Pw1 = Pw0 + 800;
    const int d0 = lane*2;

    for (int pass = 0; pass < 25; pass++) {
        const int q0 = pass*16 + w*2;
        const int q1 = q0 + 1;

        // ---- load q fragments (lane-uniform broadcast loads) ----
        float qr0[KDIM], qr1[KDIM];
        #pragma unroll
        for (int d = 0; d < KDIM; d++) {
            qr0[d] = qb[d*NPIX + q0];
            qr1[d] = qb[d*NPIX + q1];
        }
        const float* br0 = g_bias + ((size_t)h*NPIX + q0)*NPIX;
        const float* br1 = g_bias + ((size_t)h*NPIX + q1)*NPIX;

        // ---- phase A: scores + bias, write duplicated, track max ----
        float mx0 = -1e30f, mx1 = -1e30f;
        #pragma unroll
        for (int kk = 0; kk < 4; kk++) {
            const int key0 = kk*128 + lane*4;
            if (key0 < NPIX) {
                float s00=0.f,s01=0.f,s02=0.f,s03=0.f;
                float s10=0.f,s11=0.f,s12=0.f,s13=0.f;
                #pragma unroll
                for (int d = 0; d < KDIM; d++) {
                    float4 kv = *(const float4*)&Ks[d*NPIX + key0];
                    float a0 = qr0[d], a1 = qr1[d];
                    s00 += a0*kv.x; s01 += a0*kv.y; s02 += a0*kv.z; s03 += a0*kv.w;
                    s10 += a1*kv.x; s11 += a1*kv.y; s12 += a1*kv.z; s13 += a1*kv.w;
                }
                float4 bv0 = *(const float4*)&br0[key0];
                float4 bv1 = *(const float4*)&br1[key0];
                s00 = s00*0.25f + bv0.x; s01 = s01*0.25f + bv0.y;
                s02 = s02*0.25f + bv0.z; s03 = s03*0.25f + bv0.w;
                s10 = s10*0.25f + bv1.x; s11 = s11*0.25f + bv1.y;
                s12 = s12*0.25f + bv1.z; s13 = s13*0.25f + bv1.w;
                mx0 = fmaxf(mx0, fmaxf(fmaxf(s00,s01), fmaxf(s02,s03)));
                mx1 = fmaxf(mx1, fmaxf(fmaxf(s10,s11), fmaxf(s12,s13)));
                *(float4*)&Pw0[2*key0]     = make_float4(s00,s00,s01,s01);
                *(float4*)&Pw0[2*key0 + 4] = make_float4(s02,s02,s03,s03);
                *(float4*)&Pw1[2*key0]     = make_float4(s10,s10,s11,s11);
                *(float4*)&Pw1[2*key0 + 4] = make_float4(s12,s12,s13,s13);
            }
        }
        #pragma unroll
        for (int off = 16; off > 0; off >>= 1) {
            mx0 = fmaxf(mx0, __shfl_xor_sync(0xffffffffu, mx0, off));
            mx1 = fmaxf(mx1, __shfl_xor_sync(0xffffffffu, mx1, off));
        }
        __syncwarp();

        // ---- phase B: exp + denominators ----
        float den0 = 0.f, den1 = 0.f;
        for (int base = lane*8; base < 800; base += 256) {
            float4 fa = *(const float4*)&Pw0[base];
            float4 fb = *(const float4*)&Pw0[base + 4];
            float e0 = __expf(fa.x - mx0), e1 = __expf(fa.z - mx0);
            float e2 = __expf(fb.x - mx0), e3 = __expf(fb.z - mx0);
            den0 += (e0 + e1) + (e2 + e3);
            *(float4*)&Pw0[base]     = make_float4(e0,e0,e1,e1);
            *(float4*)&Pw0[base + 4] = make_float4(e2,e2,e3,e3);
            fa = *(const float4*)&Pw1[base];
            fb = *(const float4*)&Pw1[base + 4];
            e0 = __expf(fa.x - mx1); e1 = __expf(fa.z - mx1);
            e2 = __expf(fb.x - mx1); e3 = __expf(fb.z - mx1);
            den1 += (e0 + e1) + (e2 + e3);
            *(float4*)&Pw1[base]     = make_float4(e0,e0,e1,e1);
            *(float4*)&Pw1[base + 4] = make_float4(e2,e2,e3,e3);
        }
        #pragma unroll
        for (int off = 16; off > 0; off >>= 1) {
            den0 += __shfl_xor_sync(0xffffffffu, den0, off);
            den1 += __shfl_xor_sync(0xffffffffu, den1, off);
        }
        const float inv0 = 1.f / den0;
        const float inv1 = 1.f / den1;
        __syncwarp();

        // ---- phase C: PV with packed FMA ----
        ull a0 = 0ull, a1 = 0ull;
        #pragma unroll 2
        for (int k = 0; k < NPIX; k += 2) {
            ull v0 = *(const ull*)&Vs[(size_t)k*PADV + d0];
            ull v1 = *(const ull*)&Vs[(size_t)(k+1)*PADV + d0];
            ulonglong2 pp0 = *(const ulonglong2*)&Pw0[2*k];
            ulonglong2 pp1 = *(const ulonglong2*)&Pw1[2*k];
            a0 = fma2(pp0.x, v0, a0);
            a0 = fma2(pp0.y, v1, a0);
            a1 = fma2(pp1.x, v0, a1);
            a1 = fma2(pp1.y, v1, a1);
        }
        float2 r0, r1;
        r0.x = f2lo(a0)*inv0; r0.y = f2hi(a0)*inv0;
        r1.x = f2lo(a1)*inv1; r1.y = f2hi(a1)*inv1;
        *(float2*)&g_ot[((size_t)b*NPIX + q0)*DHD + h*VDIM + d0] = r0;
        *(float2*)&g_ot[((size_t)b*NPIX + q1)*DHD + h*VDIM + d0] = r1;
        __syncwarp();
    }
}

// ---------------- launch ----------------
extern "C" void kernel_launch(void* const* d_in, const int* in_sizes, int n_in,
                              void* d_out, int out_size) {
    const float* x      = (const float*)d_in[0];
    const float* qkv_w  = (const float*)d_in[1];
    const float* qkv_s  = (const float*)d_in[2];
    const float* qkv_b  = (const float*)d_in[3];
    const float* dw_w   = (const float*)d_in[4];
    const float* dw_s   = (const float*)d_in[5];
    const float* dw_b   = (const float*)d_in[6];
    const float* proj_w = (const float*)d_in[7];
    const float* proj_s = (const float*)d_in[8];
    const float* proj_b = (const float*)d_in[9];
    const float* ab     = (const float*)d_in[10];
    const float* pw1_w  = (const float*)d_in[11];
    const float* pw1_s  = (const float*)d_in[12];
    const float* pw1_b  = (const float*)d_in[13];
    const float* pw2_w  = (const float*)d_in[14];
    const float* pw2_s  = (const float*)d_in[15];
    const float* pw2_b  = (const float*)d_in[16];
    const int*   idxs   = (const int*)d_in[17];

    float *p_qkv, *p_ot, *p_y1, *p_hb;
    cudaGetSymbolAddress((void**)&p_qkv, g_qkv);
    cudaGetSymbolAddress((void**)&p_ot,  g_ot);
    cudaGetSymbolAddress((void**)&p_y1,  g_y1);
    cudaGetSymbolAddress((void**)&p_hb,  g_hb);

    // bias pipeline
    k_mtaps<<<1, 512>>>();
    k_bias1<<<(NHEAD*NPIX*SPIX + 255)/256, 256>>>(ab, idxs);
    k_bias2<<<(NHEAD*NPIX*NPIX + 255)/256, 256>>>();

    // qkv conv1x1
    k_gemm2<<<dim3(7, HQ/128, NB), 256>>>(x, qkv_w, qkv_s, qkv_b, nullptr, p_qkv, HQ, EDIM, 0);
    // depthwise 3x3 on q
    k_dwconv<<<(NB*128*NPIX + 255)/256, 256>>>(dw_w, dw_s, dw_b);

    // fused attention
    const int smem = (KDIM*NPIX + NPIX*PADV + 8*2*800) * 4;  // 182400 B
    cudaFuncSetAttribute(k_attn2, cudaFuncAttributeMaxDynamicSharedMemorySize, smem);
    k_attn2<<<NB*NHEAD, 256, smem>>>();

    // proj (relu-in, X transposed, residual x) -> y1
    k_gemm2<<<dim3(7, EDIM/128, NB), 256>>>(p_ot, proj_w, proj_s, proj_b, x, p_y1, EDIM, DHD, 1|4);
    // pw1 (relu-out) -> h
    k_gemm2<<<dim3(7, DHD/128, NB), 256>>>(p_y1, pw1_w, pw1_s, pw1_b, nullptr, p_hb, DHD, EDIM, 2);
    // pw2 (residual y1) -> out
    k_gemm2<<<dim3(7, EDIM/128, NB), 256>>>(p_hb, pw2_w, pw2_s, pw2_b, p_y1, (float*)d_out, EDIM, DHD, 0);
}

// round 5
// speedup vs baseline: 2.2835x; 2.2835x over previous
#include <cuda_runtime.h>
#include <math.h>

#define NB    32
#define EDIM  256
#define NHEAD 8
#define KDIM  16
#define VDIM  64
#define DHD   512
#define HQ    768
#define NPIX  400
#define SPIX  196
#define VTP   402   // V row stride: EVEN (8B-aligned ull for every d row)
#define SA    36    // Ws row stride
#define SBX   72    // Xs row stride

typedef unsigned long long ull;

__device__ __forceinline__ ull fma2(ull a, ull b, ull c) {
    ull d;
    asm("fma.rn.f32x2 %0, %1, %2, %3;" : "=l"(d) : "l"(a), "l"(b), "l"(c));
    return d;
}
__device__ __forceinline__ float f2lo(ull v) { return __uint_as_float((unsigned)v); }
__device__ __forceinline__ float f2hi(ull v) { return __uint_as_float((unsigned)(v >> 32)); }
__device__ __forceinline__ unsigned f2tf(float x) {
    unsigned r; asm("cvt.rna.tf32.f32 %0, %1;" : "=r"(r) : "f"(x)); return r;
}
__device__ __forceinline__ void mma8(float* c, unsigned a0, unsigned a1, unsigned a2, unsigned a3,
                                     unsigned b0, unsigned b1) {
    asm volatile("mma.sync.aligned.m16n8k8.row.col.f32.tf32.tf32.f32 "
        "{%0,%1,%2,%3}, {%4,%5,%6,%7}, {%8,%9}, {%0,%1,%2,%3};"
        : "+f"(c[0]), "+f"(c[1]), "+f"(c[2]), "+f"(c[3])
        : "r"(a0), "r"(a1), "r"(a2), "r"(a3), "r"(b0), "r"(b1));
}

// ---------------- device scratch ----------------
__device__ __align__(16) float g_qkv [NB*HQ*NPIX];
__device__ __align__(16) float g_qdw [NB*128*NPIX];
__device__ __align__(16) float g_tmpb[NHEAD*NPIX*SPIX];
__device__ __align__(16) float g_bias[NHEAD*NPIX*NPIX];
__device__ __align__(16) float g_ot  [NB*NPIX*DHD];
__device__ __align__(16) float g_y1  [NB*EDIM*NPIX];
__device__ __align__(16) float g_hb  [NB*DHD*NPIX];
__device__ int   g_midx[NPIX*4];
__device__ float g_mw  [NPIX*4];

// ---------------- bicubic taps ----------------
__global__ void k_mtaps() {
    int i = blockIdx.x*blockDim.x + threadIdx.x;
    if (i >= NPIX) return;
    double scale = (double)SPIX / (double)NPIX;
    double src = (i + 0.5)*scale - 0.5;
    double f = floor(src);
    double t = src - f;
    const double a = -0.75;
    for (int j = -1; j <= 2; j++) {
        double xx = fabs((double)j - t);
        double w;
        if (xx <= 1.0)      w = (a+2.0)*xx*xx*xx - (a+3.0)*xx*xx + 1.0;
        else if (xx < 2.0)  w = a*xx*xx*xx - 5.0*a*xx*xx + 8.0*a*xx - 4.0*a;
        else                w = 0.0;
        int idx = (int)f + j;
        idx = min(max(idx, 0), SPIX-1);
        g_midx[i*4 + (j+1)] = idx;
        g_mw  [i*4 + (j+1)] = (float)w;
    }
}

__global__ void k_bias1(const float* __restrict__ ab, const int* __restrict__ idxs) {
    int i = blockIdx.x*blockDim.x + threadIdx.x;
    if (i >= NHEAD*NPIX*SPIX) return;
    int t = i % SPIX;
    int n = (i / SPIX) % NPIX;
    int h = i / (SPIX*NPIX);
    float acc = 0.f;
    #pragma unroll
    for (int k = 0; k < 4; k++) {
        int s = g_midx[n*4+k];
        acc += g_mw[n*4+k] * ab[h*SPIX + idxs[s*SPIX + t]];
    }
    g_tmpb[i] = acc;
}

__global__ void k_bias2() {
    int i = blockIdx.x*blockDim.x + threadIdx.x;
    if (i >= NHEAD*NPIX*NPIX) return;
    int m = i % NPIX;
    int n = (i / NPIX) % NPIX;
    int h = i / (NPIX*NPIX);
    const float* trow = g_tmpb + ((size_t)h*NPIX + n)*SPIX;
    float acc = 0.f;
    #pragma unroll
    for (int k = 0; k < 4; k++)
        acc += g_mw[m*4+k] * trow[g_midx[m*4+k]];
    g_bias[i] = acc;
}

// ---------------- depthwise 3x3 ----------------
__global__ void k_dwconv(const float* __restrict__ w, const float* __restrict__ s,
                         const float* __restrict__ bia) {
    int i = blockIdx.x*blockDim.x + threadIdx.x;
    if (i >= NB*128*NPIX) return;
    int p = i % NPIX;
    int c = (i / NPIX) % 128;
    int b = i / (128*NPIX);
    int y = p / 20, x = p % 20;
    const float* src = g_qkv + ((size_t)b*HQ + c)*NPIX;
    float acc = 0.f;
    #pragma unroll
    for (int dy = -1; dy <= 1; dy++) {
        int yy = y + dy;
        if (yy < 0 || yy >= 20) continue;
        #pragma unroll
        for (int dx = -1; dx <= 1; dx++) {
            int xx = x + dx;
            if (xx < 0 || xx >= 20) continue;
            acc += w[c*9 + (dy+1)*3 + (dx+1)] * src[yy*20 + xx];
        }
    }
    g_qdw[i] = acc * s[c] + bia[c];
}

// ---------------- tf32 tensor-core GEMM ----------------
// Y[b,o,p] = post( sc[o] * (W[o,:]·act(X[b,:,p])) + bi[o] ) (+R)
// CTA tile 128(O) x 64(p), 8 warps (4x2), warp tile 32x32 = 2x4 m16n8k8.
// flags: bit0 reluIn, bit1 reluOut, bit2 X transposed [b][p][Cin]
__global__ void __launch_bounds__(256) k_gemm_t(
    const float* __restrict__ X, const float* __restrict__ W,
    const float* __restrict__ sc, const float* __restrict__ bi,
    const float* __restrict__ R, float* __restrict__ Y,
    int O, int Cin, int flags)
{
    __shared__ __align__(16) unsigned Ws[128*SA];
    __shared__ __align__(16) unsigned Xs[32*SBX];
    const int b  = blockIdx.z;
    const int oT = blockIdx.y * 128;
    const int pT = blockIdx.x * 64;
    const int t  = threadIdx.x;
    const int wid = t >> 5, lane = t & 31;
    const int g = lane >> 2, tg = lane & 3;
    const int warpM = wid & 3, warpN = wid >> 2;
    const bool reluIn  = (flags & 1) != 0;
    const bool reluOut = (flags & 2) != 0;
    const bool xT      = (flags & 4) != 0;

    float acc[2][4][4];
    #pragma unroll
    for (int mt = 0; mt < 2; mt++)
        #pragma unroll
        for (int nt = 0; nt < 4; nt++)
            #pragma unroll
            for (int i = 0; i < 4; i++) acc[mt][nt][i] = 0.f;

    for (int k0 = 0; k0 < Cin; k0 += 32) {
        // ---- load W tile [128 o][32 k] ----
        #pragma unroll
        for (int j = 0; j < 4; j++) {
            int qid = t + 256*j;
            int row = qid >> 3, kq = (qid & 7) * 4;
            float4 wv = *(const float4*)&W[(size_t)(oT + row)*Cin + k0 + kq];
            unsigned* d = &Ws[row*SA + kq];
            d[0] = f2tf(wv.x); d[1] = f2tf(wv.y);
            d[2] = f2tf(wv.z); d[3] = f2tf(wv.w);
        }
        // ---- load X tile [32 k][64 p] ----
        if (!xT) {
            #pragma unroll
            for (int j = 0; j < 2; j++) {
                int qid = t + 256*j;
                int kx = qid >> 4, pl = (qid & 15) * 4;
                int p  = pT + pl;
                float4 xv = make_float4(0.f,0.f,0.f,0.f);
                if (p < NPIX)
                    xv = *(const float4*)&X[((size_t)b*Cin + k0 + kx)*NPIX + p];
                if (reluIn) {
                    xv.x = fmaxf(xv.x,0.f); xv.y = fmaxf(xv.y,0.f);
                    xv.z = fmaxf(xv.z,0.f); xv.w = fmaxf(xv.w,0.f);
                }
                unsigned* d = &Xs[kx*SBX + pl];
                d[0] = f2tf(xv.x); d[1] = f2tf(xv.y);
                d[2] = f2tf(xv.z); d[3] = f2tf(xv.w);
            }
        } else {
            #pragma unroll
            for (int j = 0; j < 2; j++) {
                int qid = t + 256*j;
                int pl = qid >> 3, kq = (qid & 7) * 4;
                int p  = pT + pl;
                float4 xv = make_float4(0.f,0.f,0.f,0.f);
                if (p < NPIX)
                    xv = *(const float4*)&X[((size_t)b*NPIX + p)*Cin + k0 + kq];
                if (reluIn) {
                    xv.x = fmaxf(xv.x,0.f); xv.y = fmaxf(xv.y,0.f);
                    xv.z = fmaxf(xv.z,0.f); xv.w = fmaxf(xv.w,0.f);
                }
                Xs[(kq+0)*SBX + pl] = f2tf(xv.x);
                Xs[(kq+1)*SBX + pl] = f2tf(xv.y);
                Xs[(kq+2)*SBX + pl] = f2tf(xv.z);
                Xs[(kq+3)*SBX + pl] = f2tf(xv.w);
            }
        }
        __syncthreads();

        #pragma unroll
        for (int ks = 0; ks < 4; ks++) {
            const int kk = ks * 8;
            unsigned a[2][4], bf[4][2];
            #pragma unroll
            for (int mt = 0; mt < 2; mt++) {
                const unsigned* Ab = &Ws[(warpM*32 + mt*16 + g)*SA + kk + tg];
                a[mt][0] = Ab[0];
                a[mt][1] = Ab[8*SA];
                a[mt][2] = Ab[4];
                a[mt][3] = Ab[8*SA + 4];
            }
            #pragma unroll
            for (int nt = 0; nt < 4; nt++) {
                const unsigned* Bb = &Xs[(kk + tg)*SBX + warpN*32 + nt*8 + g];
                bf[nt][0] = Bb[0];
                bf[nt][1] = Bb[4*SBX];
            }
            #pragma unroll
            for (int mt = 0; mt < 2; mt++)
                #pragma unroll
                for (int nt = 0; nt < 4; nt++)
                    mma8(acc[mt][nt], a[mt][0], a[mt][1], a[mt][2], a[mt][3],
                         bf[nt][0], bf[nt][1]);
        }
        __syncthreads();
    }

    // ---- epilogue ----
    #pragma unroll
    for (int mt = 0; mt < 2; mt++) {
        const int o0 = oT + warpM*32 + mt*16 + g;
        const int o1 = o0 + 8;
        const float s0 = sc[o0], bb0 = bi[o0];
        const float s1 = sc[o1], bb1 = bi[o1];
        #pragma unroll
        for (int nt = 0; nt < 4; nt++) {
            const int p = pT + warpN*32 + nt*8 + 2*tg;
            if (p < NPIX) {
                float2 v0, v1;
                v0.x = acc[mt][nt][0]*s0 + bb0;
                v0.y = acc[mt][nt][1]*s0 + bb0;
                v1.x = acc[mt][nt][2]*s1 + bb1;
                v1.y = acc[mt][nt][3]*s1 + bb1;
                if (reluOut) {
                    v0.x = fmaxf(v0.x,0.f); v0.y = fmaxf(v0.y,0.f);
                    v1.x = fmaxf(v1.x,0.f); v1.y = fmaxf(v1.y,0.f);
                }
                const size_t off0 = ((size_t)b*O + o0)*NPIX + p;
                const size_t off1 = ((size_t)b*O + o1)*NPIX + p;
                if (R) {
                    float2 r0 = *(const float2*)&R[off0];
                    float2 r1 = *(const float2*)&R[off1];
                    v0.x += r0.x; v0.y += r0.y;
                    v1.x += r1.x; v1.y += r1.y;
                }
                *(float2*)&Y[off0] = v0;
                *(float2*)&Y[off1] = v1;
            }
        }
    }
}

// ---------------- fused attention ----------------
// One CTA per (b,h), 128 threads (4 warps). Each warp owns 8 query rows per
// pass (13 passes). V in [d][key] layout, row stride VTP=402 (EVEN -> every
// per-d row pointer is 8B aligned). PV uses f32x2 packed over key pairs;
// P smem reads are lane-uniform broadcasts. Output transposed: g_ot[b][q][hd].
__global__ void __launch_bounds__(128) k_attn3() {
    extern __shared__ float sm[];
    float* Qs = sm;                 // [16][400]
    float* Ks = Qs + KDIM*NPIX;     // [16][400]
    float* Vt = Ks + KDIM*NPIX;     // [64][VTP]
    float* Ps = Vt + VDIM*VTP;      // [4 warps][8][400]
    const int bh = blockIdx.x;
    const int b = bh >> 3, h = bh & 7;
    const int tid = threadIdx.x;

    const float* qb = g_qdw + ((size_t)b*128 + h*KDIM)*NPIX;
    const float* kb = g_qkv + ((size_t)b*HQ + 128 + h*KDIM)*NPIX;
    const float* vb = g_qkv + ((size_t)b*HQ + 256 + h*VDIM)*NPIX;

    for (int i = tid; i < KDIM*NPIX; i += 128) { Qs[i] = qb[i]; Ks[i] = kb[i]; }
    for (int i = tid; i < VDIM*NPIX; i += 128) {
        int d = i / NPIX, p = i - d*NPIX;
        Vt[d*VTP + p] = vb[i];
    }
    __syncthreads();

    const int w = tid >> 5, lane = tid & 31;
    float* Pw = Ps + (size_t)w*8*NPIX;
    const int d0 = lane*2;
    const float* vr0 = &Vt[(size_t)d0*VTP];
    const float* vr1 = &Vt[(size_t)(d0+1)*VTP];

    for (int pass = 0; pass < 13; pass++) {
        const int q0 = pass*32 + w*8;
        if (q0 >= NPIX) continue;   // warp-uniform; no block syncs below

        float mx[8];
        #pragma unroll
        for (int qi = 0; qi < 8; qi++) mx[qi] = -1e30f;

        // ---- phase A: scores + bias ----
        #pragma unroll
        for (int ck = 0; ck < 4; ck++) {
            const int key0 = ck*128 + lane*4;
            if (key0 < NPIX) {
                float4 s[8];
                #pragma unroll
                for (int qi = 0; qi < 8; qi++) s[qi] = make_float4(0.f,0.f,0.f,0.f);
                #pragma unroll
                for (int d = 0; d < KDIM; d++) {
                    float4 kv = *(const float4*)&Ks[d*NPIX + key0];
                    float4 qa = *(const float4*)&Qs[d*NPIX + q0];
                    float4 qc = *(const float4*)&Qs[d*NPIX + q0 + 4];
                    const float qv[8] = {qa.x,qa.y,qa.z,qa.w, qc.x,qc.y,qc.z,qc.w};
                    #pragma unroll
                    for (int qi = 0; qi < 8; qi++) {
                        s[qi].x += qv[qi]*kv.x; s[qi].y += qv[qi]*kv.y;
                        s[qi].z += qv[qi]*kv.z; s[qi].w += qv[qi]*kv.w;
                    }
                }
                #pragma unroll
                for (int qi = 0; qi < 8; qi++) {
                    float4 bv = *(const float4*)&g_bias[((size_t)h*NPIX + q0 + qi)*NPIX + key0];
                    s[qi].x = s[qi].x*0.25f + bv.x;
                    s[qi].y = s[qi].y*0.25f + bv.y;
                    s[qi].z = s[qi].z*0.25f + bv.z;
                    s[qi].w = s[qi].w*0.25f + bv.w;
                    mx[qi] = fmaxf(mx[qi], fmaxf(fmaxf(s[qi].x, s[qi].y),
                                                 fmaxf(s[qi].z, s[qi].w)));
                    *(float4*)&Pw[qi*NPIX + key0] = s[qi];
                }
            }
        }
        #pragma unroll
        for (int qi = 0; qi < 8; qi++)
            #pragma unroll
            for (int off = 16; off > 0; off >>= 1)
                mx[qi] = fmaxf(mx[qi], __shfl_xor_sync(0xffffffffu, mx[qi], off));

        // ---- phase B: exp + denominators (same-lane readback) ----
        float inv[8];
        #pragma unroll
        for (int qi = 0; qi < 8; qi++) {
            float den = 0.f;
            #pragma unroll
            for (int jj = 0; jj < 4; jj++) {
                const int i = jj*128 + lane*4;
                if (i < NPIX) {
                    float4 v = *(const float4*)&Pw[qi*NPIX + i];
                    v.x = __expf(v.x - mx[qi]);
                    v.y = __expf(v.y - mx[qi]);
                    v.z = __expf(v.z - mx[qi]);
                    v.w = __expf(v.w - mx[qi]);
                    den += (v.x + v.y) + (v.z + v.w);
                    *(float4*)&Pw[qi*NPIX + i] = v;
                }
            }
            #pragma unroll
            for (int off = 16; off > 0; off >>= 1)
                den += __shfl_xor_sync(0xffffffffu, den, off);
            inv[qi] = 1.f / den;
        }
        __syncwarp();

        // ---- phase C: PV, f32x2 packed over key pairs (8B aligned loads) ----
        ull acc0[8], acc1[8];
        #pragma unroll
        for (int qi = 0; qi < 8; qi++) { acc0[qi] = 0ull; acc1[qi] = 0ull; }
        #pragma unroll 2
        for (int k = 0; k < NPIX; k += 4) {
            ull v00 = *(const ull*)&vr0[k];
            ull v01 = *(const ull*)&vr0[k+2];
            ull v10 = *(const ull*)&vr1[k];
            ull v11 = *(const ull*)&vr1[k+2];
            #pragma unroll
            for (int qi = 0; qi < 8; qi++) {
                ull p0 = *(const ull*)&Pw[qi*NPIX + k];
                ull p1 = *(const ull*)&Pw[qi*NPIX + k + 2];
                acc0[qi] = fma2(p0, v00, acc0[qi]);
                acc0[qi] = fma2(p1, v01, acc0[qi]);
                acc1[qi] = fma2(p0, v10, acc1[qi]);
                acc1[qi] = fma2(p1, v11, acc1[qi]);
            }
        }
        #pragma unroll
        for (int qi = 0; qi < 8; qi++) {
            float2 r;
            r.x = (f2lo(acc0[qi]) + f2hi(acc0[qi])) * inv[qi];
            r.y = (f2lo(acc1[qi]) + f2hi(acc1[qi])) * inv[qi];
            *(float2*)&g_ot[((size_t)b*NPIX + q0 + qi)*DHD + h*VDIM + d0] = r;
        }
        __syncwarp();
    }
}

// ---------------- launch ----------------
extern "C" void kernel_launch(void* const* d_in, const int* in_sizes, int n_in,
                              void* d_out, int out_size) {
    const float* x      = (const float*)d_in[0];
    const float* qkv_w  = (const float*)d_in[1];
    const float* qkv_s  = (const float*)d_in[2];
    const float* qkv_b  = (const float*)d_in[3];
    const float* dw_w   = (const float*)d_in[4];
    const float* dw_s   = (const float*)d_in[5];
    const float* dw_b   = (const float*)d_in[6];
    const float* proj_w = (const float*)d_in[7];
    const float* proj_s = (const float*)d_in[8];
    const float* proj_b = (const float*)d_in[9];
    const float* ab     = (const float*)d_in[10];
    const float* pw1_w  = (const float*)d_in[11];
    const float* pw1_s  = (const float*)d_in[12];
    const float* pw1_b  = (const float*)d_in[13];
    const float* pw2_w  = (const float*)d_in[14];
    const float* pw2_s  = (const float*)d_in[15];
    const float* pw2_b  = (const float*)d_in[16];
    const int*   idxs   = (const int*)d_in[17];

    float *p_qkv, *p_ot, *p_y1, *p_hb;
    cudaGetSymbolAddress((void**)&p_qkv, g_qkv);
    cudaGetSymbolAddress((void**)&p_ot,  g_ot);
    cudaGetSymbolAddress((void**)&p_y1,  g_y1);
    cudaGetSymbolAddress((void**)&p_hb,  g_hb);

    // bias pipeline
    k_mtaps<<<1, 512>>>();
    k_bias1<<<(NHEAD*NPIX*SPIX + 255)/256, 256>>>(ab, idxs);
    k_bias2<<<(NHEAD*NPIX*NPIX + 255)/256, 256>>>();

    // qkv conv1x1 (tf32 mma)
    k_gemm_t<<<dim3(7, HQ/128, NB), 256>>>(x, qkv_w, qkv_s, qkv_b, nullptr, p_qkv, HQ, EDIM, 0);
    // depthwise 3x3 on q
    k_dwconv<<<(NB*128*NPIX + 255)/256, 256>>>(dw_w, dw_s, dw_b);

    // fused attention
    const int smem = (KDIM*NPIX + KDIM*NPIX + VDIM*VTP + 4*8*NPIX) * 4; // 205312 B
    cudaFuncSetAttribute(k_attn3, cudaFuncAttributeMaxDynamicSharedMemorySize, smem);
    k_attn3<<<NB*NHEAD, 128, smem>>>();

    // proj (relu-in, X transposed, residual x) -> y1
    k_gemm_t<<<dim3(7, EDIM/128, NB), 256>>>(p_ot, proj_w, proj_s, proj_b, x, p_y1, EDIM, DHD, 1|4);
    // pw1 (relu-out) -> h
    k_gemm_t<<<dim3(7, DHD/128, NB), 256>>>(p_y1, pw1_w, pw1_s, pw1_b, nullptr, p_hb, DHD, EDIM, 2);
    // pw2 (residual y1) -> out
    k_gemm_t<<<dim3(7, EDIM/128, NB), 256>>>(p_hb, pw2_w, pw2_s, pw2_b, p_y1, (float*)d_out, EDIM, DHD, 0);
}

// round 7
// speedup vs baseline: 2.8912x; 1.2661x over previous
#include <cuda_runtime.h>
#include <math.h>

#define NB    32
#define EDIM  256
#define NHEAD 8
#define KDIM  16
#define VDIM  64
#define DHD   512
#define HQ    768
#define NPIX  400
#define SPIX  196
#define VTP   402   // V row stride (even -> 8B aligned; 201 odd -> conflict-free LDS.64)
#define SA    36    // Ws row stride
#define SBX   72    // Xs row stride
#define QSC   0.3606737602222409f   // 0.25 * log2(e)
#define L2E   1.4426950408889634f

typedef unsigned long long ull;

__device__ __forceinline__ ull fma2(ull a, ull b, ull c) {
    ull d;
    asm("fma.rn.f32x2 %0, %1, %2, %3;" : "=l"(d) : "l"(a), "l"(b), "l"(c));
    return d;
}
__device__ __forceinline__ float f2lo(ull v) { return __uint_as_float((unsigned)v); }
__device__ __forceinline__ float f2hi(ull v) { return __uint_as_float((unsigned)(v >> 32)); }
__device__ __forceinline__ unsigned f2tf(float x) {
    unsigned r; asm("cvt.rna.tf32.f32 %0, %1;" : "=r"(r) : "f"(x)); return r;
}
__device__ __forceinline__ float ex2f(float x) {
    float y; asm("ex2.approx.ftz.f32 %0, %1;" : "=f"(y) : "f"(x)); return y;
}
__device__ __forceinline__ void mma8(float* c, unsigned a0, unsigned a1, unsigned a2, unsigned a3,
                                     unsigned b0, unsigned b1) {
    asm volatile("mma.sync.aligned.m16n8k8.row.col.f32.tf32.tf32.f32 "
        "{%0,%1,%2,%3}, {%4,%5,%6,%7}, {%8,%9}, {%0,%1,%2,%3};"
        : "+f"(c[0]), "+f"(c[1]), "+f"(c[2]), "+f"(c[3])
        : "r"(a0), "r"(a1), "r"(a2), "r"(a3), "r"(b0), "r"(b1));
}

// ---------------- device scratch ----------------
__device__ __align__(16) float g_qkv [NB*HQ*NPIX];
__device__ __align__(16) float g_qdw [NB*128*NPIX];   // pre-scaled by QSC
__device__ __align__(16) float g_tmpb[NHEAD*NPIX*SPIX];
__device__ __align__(16) float g_bias[NHEAD*NPIX*NPIX]; // pre-scaled by L2E
__device__ __align__(16) float g_ot  [NB*NPIX*DHD];
__device__ __align__(16) float g_y1  [NB*EDIM*NPIX];
__device__ __align__(16) float g_hb  [NB*DHD*NPIX];
__device__ int   g_midx[NPIX*4];
__device__ float g_mw  [NPIX*4];

// ---------------- bicubic taps ----------------
__global__ void k_mtaps() {
    int i = blockIdx.x*blockDim.x + threadIdx.x;
    if (i >= NPIX) return;
    double scale = (double)SPIX / (double)NPIX;
    double src = (i + 0.5)*scale - 0.5;
    double f = floor(src);
    double t = src - f;
    const double a = -0.75;
    for (int j = -1; j <= 2; j++) {
        double xx = fabs((double)j - t);
        double w;
        if (xx <= 1.0)      w = (a+2.0)*xx*xx*xx - (a+3.0)*xx*xx + 1.0;
        else if (xx < 2.0)  w = a*xx*xx*xx - 5.0*a*xx*xx + 8.0*a*xx - 4.0*a;
        else                w = 0.0;
        int idx = (int)f + j;
        idx = min(max(idx, 0), SPIX-1);
        g_midx[i*4 + (j+1)] = idx;
        g_mw  [i*4 + (j+1)] = (float)w;
    }
}

__global__ void k_bias1(const float* __restrict__ ab, const int* __restrict__ idxs) {
    int i = blockIdx.x*blockDim.x + threadIdx.x;
    if (i >= NHEAD*NPIX*SPIX) return;
    int t = i % SPIX;
    int n = (i / SPIX) % NPIX;
    int h = i / (SPIX*NPIX);
    float acc = 0.f;
    #pragma unroll
    for (int k = 0; k < 4; k++) {
        int s = g_midx[n*4+k];
        acc += g_mw[n*4+k] * ab[h*SPIX + idxs[s*SPIX + t]];
    }
    g_tmpb[i] = acc;
}

__global__ void k_bias2() {
    int i = blockIdx.x*blockDim.x + threadIdx.x;
    if (i >= NHEAD*NPIX*NPIX) return;
    int m = i % NPIX;
    int n = (i / NPIX) % NPIX;
    int h = i / (NPIX*NPIX);
    const float* trow = g_tmpb + ((size_t)h*NPIX + n)*SPIX;
    float acc = 0.f;
    #pragma unroll
    for (int k = 0; k < 4; k++)
        acc += g_mw[m*4+k] * trow[g_midx[m*4+k]];
    g_bias[i] = acc * L2E;   // log2 domain for ex2-based softmax
}

// ---------------- depthwise 3x3 (output pre-scaled by QSC) ----------------
__global__ void k_dwconv(const float* __restrict__ w, const float* __restrict__ s,
                         const float* __restrict__ bia) {
    int i = blockIdx.x*blockDim.x + threadIdx.x;
    if (i >= NB*128*NPIX) return;
    int p = i % NPIX;
    int c = (i / NPIX) % 128;
    int b = i / (128*NPIX);
    int y = p / 20, x = p % 20;
    const float* src = g_qkv + ((size_t)b*HQ + c)*NPIX;
    float acc = 0.f;
    #pragma unroll
    for (int dy = -1; dy <= 1; dy++) {
        int yy = y + dy;
        if (yy < 0 || yy >= 20) continue;
        #pragma unroll
        for (int dx = -1; dx <= 1; dx++) {
            int xx = x + dx;
            if (xx < 0 || xx >= 20) continue;
            acc += w[c*9 + (dy+1)*3 + (dx+1)] * src[yy*20 + xx];
        }
    }
    g_qdw[i] = (acc * s[c] + bia[c]) * QSC;
}

// ---------------- tf32 tensor-core GEMM with register prefetch ----------------
// flags: bit0 reluIn, bit1 reluOut, bit2 X transposed [b][p][Cin]
__device__ __forceinline__ void gemm_loadW(const float* __restrict__ W, int Cin,
                                           int oT, int k0, int t, float4* wv) {
    #pragma unroll
    for (int j = 0; j < 4; j++) {
        int qid = t + 256*j;
        int row = qid >> 3, kq = (qid & 7) * 4;
        wv[j] = *(const float4*)&W[(size_t)(oT + row)*Cin + k0 + kq];
    }
}
__device__ __forceinline__ void gemm_loadX(const float* __restrict__ X, int Cin, int b,
                                           int pT, int k0, int t, bool xT, float4* xv) {
    #pragma unroll
    for (int j = 0; j < 2; j++) {
        int qid = t + 256*j;
        float4 v = make_float4(0.f,0.f,0.f,0.f);
        if (!xT) {
            int kx = qid >> 4, pl = (qid & 15) * 4;
            int p  = pT + pl;
            if (p < NPIX) v = *(const float4*)&X[((size_t)b*Cin + k0 + kx)*NPIX + p];
        } else {
            int pl = qid >> 3, kq = (qid & 7) * 4;
            int p  = pT + pl;
            if (p < NPIX) v = *(const float4*)&X[((size_t)b*NPIX + p)*Cin + k0 + kq];
        }
        xv[j] = v;
    }
}
__global__ void __launch_bounds__(256) k_gemm_t(
    const float* __restrict__ X, const float* __restrict__ W,
    const float* __restrict__ sc, const float* __restrict__ bi,
    const float* __restrict__ R, float* __restrict__ Y,
    int O, int Cin, int flags)
{
    __shared__ __align__(16) unsigned Ws[128*SA];
    __shared__ __align__(16) unsigned Xs[32*SBX];
    const int b  = blockIdx.z;
    const int oT = blockIdx.y * 128;
    const int pT = blockIdx.x * 64;
    const int t  = threadIdx.x;
    const int wid = t >> 5, lane = t & 31;
    const int g = lane >> 2, tg = lane & 3;
    const int warpM = wid & 3, warpN = wid >> 2;
    const bool reluIn  = (flags & 1) != 0;
    const bool reluOut = (flags & 2) != 0;
    const bool xT      = (flags & 4) != 0;

    float acc[2][4][4];
    #pragma unroll
    for (int mt = 0; mt < 2; mt++)
        #pragma unroll
        for (int nt = 0; nt < 4; nt++)
            #pragma unroll
            for (int i = 0; i < 4; i++) acc[mt][nt][i] = 0.f;

    const int nchunk = Cin >> 5;
    float4 wv[4], xv[2];
    gemm_loadW(W, Cin, oT, 0, t, wv);
    gemm_loadX(X, Cin, b, pT, 0, t, xT, xv);

    for (int c = 0; c < nchunk; c++) {
        // ---- store prefetched tile to smem (with cvt/relu) ----
        #pragma unroll
        for (int j = 0; j < 4; j++) {
            int qid = t + 256*j;
            int row = qid >> 3, kq = (qid & 7) * 4;
            unsigned* d = &Ws[row*SA + kq];
            d[0] = f2tf(wv[j].x); d[1] = f2tf(wv[j].y);
            d[2] = f2tf(wv[j].z); d[3] = f2tf(wv[j].w);
        }
        #pragma unroll
        for (int j = 0; j < 2; j++) {
            float4 v = xv[j];
            if (reluIn) {
                v.x = fmaxf(v.x,0.f); v.y = fmaxf(v.y,0.f);
                v.z = fmaxf(v.z,0.f); v.w = fmaxf(v.w,0.f);
            }
            int qid = t + 256*j;
            if (!xT) {
                int kx = qid >> 4, pl = (qid & 15) * 4;
                unsigned* d = &Xs[kx*SBX + pl];
                d[0] = f2tf(v.x); d[1] = f2tf(v.y);
                d[2] = f2tf(v.z); d[3] = f2tf(v.w);
            } else {
                int pl = qid >> 3, kq = (qid & 7) * 4;
                Xs[(kq+0)*SBX + pl] = f2tf(v.x);
                Xs[(kq+1)*SBX + pl] = f2tf(v.y);
                Xs[(kq+2)*SBX + pl] = f2tf(v.z);
                Xs[(kq+3)*SBX + pl] = f2tf(v.w);
            }
        }
        __syncthreads();

        // ---- prefetch next chunk (LDG overlaps the MMAs below) ----
        if (c + 1 < nchunk) {
            gemm_loadW(W, Cin, oT, (c+1)*32, t, wv);
            gemm_loadX(X, Cin, b, pT, (c+1)*32, t, xT, xv);
        }

        #pragma unroll
        for (int ks = 0; ks < 4; ks++) {
            const int kk = ks * 8;
            unsigned a[2][4], bf[4][2];
            #pragma unroll
            for (int mt = 0; mt < 2; mt++) {
                const unsigned* Ab = &Ws[(warpM*32 + mt*16 + g)*SA + kk + tg];
                a[mt][0] = Ab[0];
                a[mt][1] = Ab[8*SA];
                a[mt][2] = Ab[4];
                a[mt][3] = Ab[8*SA + 4];
            }
            #pragma unroll
            for (int nt = 0; nt < 4; nt++) {
                const unsigned* Bb = &Xs[(kk + tg)*SBX + warpN*32 + nt*8 + g];
                bf[nt][0] = Bb[0];
                bf[nt][1] = Bb[4*SBX];
            }
            #pragma unroll
            for (int mt = 0; mt < 2; mt++)
                #pragma unroll
                for (int nt = 0; nt < 4; nt++)
                    mma8(acc[mt][nt], a[mt][0], a[mt][1], a[mt][2], a[mt][3],
                         bf[nt][0], bf[nt][1]);
        }
        __syncthreads();
    }

    // ---- epilogue ----
    #pragma unroll
    for (int mt = 0; mt < 2; mt++) {
        const int o0 = oT + warpM*32 + mt*16 + g;
        const int o1 = o0 + 8;
        const float s0 = sc[o0], bb0 = bi[o0];
        const float s1 = sc[o1], bb1 = bi[o1];
        #pragma unroll
        for (int nt = 0; nt < 4; nt++) {
            const int p = pT + warpN*32 + nt*8 + 2*tg;
            if (p < NPIX) {
                float2 v0, v1;
                v0.x = acc[mt][nt][0]*s0 + bb0;
                v0.y = acc[mt][nt][1]*s0 + bb0;
                v1.x = acc[mt][nt][2]*s1 + bb1;
                v1.y = acc[mt][nt][3]*s1 + bb1;
                if (reluOut) {
                    v0.x = fmaxf(v0.x,0.f); v0.y = fmaxf(v0.y,0.f);
                    v1.x = fmaxf(v1.x,0.f); v1.y = fmaxf(v1.y,0.f);
                }
                const size_t off0 = ((size_t)b*O + o0)*NPIX + p;
                const size_t off1 = ((size_t)b*O + o1)*NPIX + p;
                if (R) {
                    float2 r0 = *(const float2*)&R[off0];
                    float2 r1 = *(const float2*)&R[off1];
                    v0.x += r0.x; v0.y += r0.y;
                    v1.x += r1.x; v1.y += r1.y;
                }
                *(float2*)&Y[off0] = v0;
                *(float2*)&Y[off1] = v1;
            }
        }
    }
}

// ---------------- fused attention v4 ----------------
// One CTA per (b,h), 256 threads (8 warps). Each warp owns 4 query rows per
// pass (13 passes, last pass only warps 0..3). Scores kept in registers
// through softmax; exp'd P written once to smem for the PV phase.
// Each lane owns V rows d=lane and d=lane+32 (8B-word stride 201, odd ->
// conflict-free LDS.64). P reads are 16B-aligned ulonglong2 broadcasts.
__global__ void __launch_bounds__(256) k_attn4() {
    extern __shared__ float sm[];
    float* Qs = sm;                 // [16][400]  pre-scaled by QSC
    float* Ks = Qs + KDIM*NPIX;     // [16][400]
    float* Vt = Ks + KDIM*NPIX;     // [64][VTP]
    float* Ps = Vt + VDIM*VTP;      // [8 warps][4 q][400]
    const int bh = blockIdx.x;
    const int b = bh >> 3, h = bh & 7;
    const int tid = threadIdx.x;

    const float* qb = g_qdw + ((size_t)b*128 + h*KDIM)*NPIX;
    const float* kb = g_qkv + ((size_t)b*HQ + 128 + h*KDIM)*NPIX;
    const float* vb = g_qkv + ((size_t)b*HQ + 256 + h*VDIM)*NPIX;

    for (int i = tid; i < KDIM*NPIX; i += 256) { Qs[i] = qb[i]; Ks[i] = kb[i]; }
    for (int i = tid; i < VDIM*NPIX; i += 256) {
        int d = i / NPIX, p = i - d*NPIX;
        Vt[d*VTP + p] = vb[i];
    }
    __syncthreads();

    const int w = tid >> 5, lane = tid & 31;
    float* Pw = Ps + (size_t)w*4*NPIX;
    const float* vrA = &Vt[(size_t)lane*VTP];          // V row d=lane
    const float* vrB = &Vt[(size_t)(lane+32)*VTP];     // V row d=lane+32

    for (int pass = 0; pass < 13; pass++) {
        const int q0 = pass*32 + w*4;
        if (q0 >= NPIX) continue;   // warp-uniform; no block syncs below

        // ---- phase A: scores (log2 domain) into registers ----
        float4 sreg[4][4];          // [ck][qi]
        float mx0 = -1e30f, mx1 = -1e30f, mx2 = -1e30f, mx3 = -1e30f;
        #pragma unroll
        for (int ck = 0; ck < 4; ck++) {
            const int key0 = ck*128 + lane*4;
            float4 s0 = make_float4(0.f,0.f,0.f,0.f);
            float4 s1 = s0, s2 = s0, s3 = s0;
            if (key0 < NPIX) {
                #pragma unroll
                for (int d = 0; d < KDIM; d++) {
                    float4 kv = *(const float4*)&Ks[d*NPIX + key0];
                    float4 qv = *(const float4*)&Qs[d*NPIX + q0];
                    s0.x += qv.x*kv.x; s0.y += qv.x*kv.y; s0.z += qv.x*kv.z; s0.w += qv.x*kv.w;
                    s1.x += qv.y*kv.x; s1.y += qv.y*kv.y; s1.z += qv.y*kv.z; s1.w += qv.y*kv.w;
                    s2.x += qv.z*kv.x; s2.y += qv.z*kv.y; s2.z += qv.z*kv.z; s2.w += qv.z*kv.w;
                    s3.x += qv.w*kv.x; s3.y += qv.w*kv.y; s3.z += qv.w*kv.z; s3.w += qv.w*kv.w;
                }
                const float* bb = &g_bias[((size_t)h*NPIX + q0)*NPIX + key0];
                float4 b0 = *(const float4*)(bb);
                float4 b1 = *(const float4*)(bb + NPIX);
                float4 b2 = *(const float4*)(bb + 2*NPIX);
                float4 b3 = *(const float4*)(bb + 3*NPIX);
                s0.x += b0.x; s0.y += b0.y; s0.z += b0.z; s0.w += b0.w;
                s1.x += b1.x; s1.y += b1.y; s1.z += b1.z; s1.w += b1.w;
                s2.x += b2.x; s2.y += b2.y; s2.z += b2.z; s2.w += b2.w;
                s3.x += b3.x; s3.y += b3.y; s3.z += b3.z; s3.w += b3.w;
                mx0 = fmaxf(mx0, fmaxf(fmaxf(s0.x,s0.y), fmaxf(s0.z,s0.w)));
                mx1 = fmaxf(mx1, fmaxf(fmaxf(s1.x,s1.y), fmaxf(s1.z,s1.w)));
                mx2 = fmaxf(mx2, fmaxf(fmaxf(s2.x,s2.y), fmaxf(s2.z,s2.w)));
                mx3 = fmaxf(mx3, fmaxf(fmaxf(s3.x,s3.y), fmaxf(s3.z,s3.w)));
            }
            sreg[ck][0] = s0; sreg[ck][1] = s1; sreg[ck][2] = s2; sreg[ck][3] = s3;
        }
        #pragma unroll
        for (int off = 16; off > 0; off >>= 1) {
            mx0 = fmaxf(mx0, __shfl_xor_sync(0xffffffffu, mx0, off));
            mx1 = fmaxf(mx1, __shfl_xor_sync(0xffffffffu, mx1, off));
            mx2 = fmaxf(mx2, __shfl_xor_sync(0xffffffffu, mx2, off));
            mx3 = fmaxf(mx3, __shfl_xor_sync(0xffffffffu, mx3, off));
        }

        // ---- exp (base-2) + denominators, write P ----
        const float mxs[4] = {mx0, mx1, mx2, mx3};
        float dens[4] = {0.f, 0.f, 0.f, 0.f};
        #pragma unroll
        for (int ck = 0; ck < 4; ck++) {
            const int key0 = ck*128 + lane*4;
            if (key0 < NPIX) {
                #pragma unroll
                for (int qi = 0; qi < 4; qi++) {
                    float4 s = sreg[ck][qi];
                    float m = mxs[qi];
                    float4 e;
                    e.x = ex2f(s.x - m); e.y = ex2f(s.y - m);
                    e.z = ex2f(s.z - m); e.w = ex2f(s.w - m);
                    dens[qi] += (e.x + e.y) + (e.z + e.w);
                    *(float4*)&Pw[qi*NPIX + key0] = e;
                }
            }
        }
        float den0 = dens[0], den1 = dens[1], den2 = dens[2], den3 = dens[3];
        #pragma unroll
        for (int off = 16; off > 0; off >>= 1) {
            den0 += __shfl_xor_sync(0xffffffffu, den0, off);
            den1 += __shfl_xor_sync(0xffffffffu, den1, off);
            den2 += __shfl_xor_sync(0xffffffffu, den2, off);
            den3 += __shfl_xor_sync(0xffffffffu, den3, off);
        }
        const float inv[4] = {1.f/den0, 1.f/den1, 1.f/den2, 1.f/den3};
        __syncwarp();

        // ---- phase C: PV with f32x2 packed over key pairs ----
        ull accA[4], accB[4];
        #pragma unroll
        for (int qi = 0; qi < 4; qi++) { accA[qi] = 0ull; accB[qi] = 0ull; }
        #pragma unroll 2
        for (int k = 0; k < NPIX; k += 4) {
            ull vA0 = *(const ull*)&vrA[k];
            ull vA1 = *(const ull*)&vrA[k+2];
            ull vB0 = *(const ull*)&vrB[k];
            ull vB1 = *(const ull*)&vrB[k+2];
            #pragma unroll
            for (int qi = 0; qi < 4; qi++) {
                ulonglong2 pp = *(const ulonglong2*)&Pw[qi*NPIX + k];
                accA[qi] = fma2(pp.x, vA0, accA[qi]);
                accA[qi] = fma2(pp.y, vA1, accA[qi]);
                accB[qi] = fma2(pp.x, vB0, accB[qi]);
                accB[qi] = fma2(pp.y, vB1, accB[qi]);
            }
        }
        #pragma unroll
        for (int qi = 0; qi < 4; qi++) {
            float* orow = &g_ot[((size_t)b*NPIX + q0 + qi)*DHD + h*VDIM];
            orow[lane]      = (f2lo(accA[qi]) + f2hi(accA[qi])) * inv[qi];
            orow[lane + 32] = (f2lo(accB[qi]) + f2hi(accB[qi])) * inv[qi];
        }
        __syncwarp();
    }
}

// ---------------- launch ----------------
extern "C" void kernel_launch(void* const* d_in, const int* in_sizes, int n_in,
                              void* d_out, int out_size) {
    const float* x      = (const float*)d_in[0];
    const float* qkv_w  = (const float*)d_in[1];
    const float* qkv_s  = (const float*)d_in[2];
    const float* qkv_b  = (const float*)d_in[3];
    const float* dw_w   = (const float*)d_in[4];
    const float* dw_s   = (const float*)d_in[5];
    const float* dw_b   = (const float*)d_in[6];
    const float* proj_w = (const float*)d_in[7];
    const float* proj_s = (const float*)d_in[8];
    const float* proj_b = (const float*)d_in[9];
    const float* ab     = (const float*)d_in[10];
    const float* pw1_w  = (const float*)d_in[11];
    const float* pw1_s  = (const float*)d_in[12];
    const float* pw1_b  = (const float*)d_in[13];
    const float* pw2_w  = (const float*)d_in[14];
    const float* pw2_s  = (const float*)d_in[15];
    const float* pw2_b  = (const float*)d_in[16];
    const int*   idxs   = (const int*)d_in[17];

    float *p_qkv, *p_ot, *p_y1, *p_hb;
    cudaGetSymbolAddress((void**)&p_qkv, g_qkv);
    cudaGetSymbolAddress((void**)&p_ot,  g_ot);
    cudaGetSymbolAddress((void**)&p_y1,  g_y1);
    cudaGetSymbolAddress((void**)&p_hb,  g_hb);

    // bias pipeline
    k_mtaps<<<1, 512>>>();
    k_bias1<<<(NHEAD*NPIX*SPIX + 255)/256, 256>>>(ab, idxs);
    k_bias2<<<(NHEAD*NPIX*NPIX + 255)/256, 256>>>();

    // qkv conv1x1 (tf32 mma)
    k_gemm_t<<<dim3(7, HQ/128, NB), 256>>>(x, qkv_w, qkv_s, qkv_b, nullptr, p_qkv, HQ, EDIM, 0);
    // depthwise 3x3 on q (pre-scaled for log2-domain softmax)
    k_dwconv<<<(NB*128*NPIX + 255)/256, 256>>>(dw_w, dw_s, dw_b);

    // fused attention
    const int smem = (KDIM*NPIX + KDIM*NPIX + VDIM*VTP + 8*4*NPIX) * 4; // 205312 B
    cudaFuncSetAttribute(k_attn4, cudaFuncAttributeMaxDynamicSharedMemorySize, smem);
    k_attn4<<<NB*NHEAD, 256, smem>>>();

    // proj (relu-in, X transposed, residual x) -> y1
    k_gemm_t<<<dim3(7, EDIM/128, NB), 256>>>(p_ot, proj_w, proj_s, proj_b, x, p_y1, EDIM, DHD, 1|4);
    // pw1 (relu-out) -> h
    k_gemm_t<<<dim3(7, DHD/128, NB), 256>>>(p_y1, pw1_w, pw1_s, pw1_b, nullptr, p_hb, DHD, EDIM, 2);
    // pw2 (residual y1) -> out
    k_gemm_t<<<dim3(7, EDIM/128, NB), 256>>>(p_hb, pw2_w, pw2_s, pw2_b, p_y1, (float*)d_out, EDIM, DHD, 0);
}

// round 9
// speedup vs baseline: 4.3720x; 1.5122x over previous
#include <cuda_runtime.h>
#include <cuda_fp16.h>
#include <math.h>

#define NB    32
#define EDIM  256
#define NHEAD 8
#define KDIM  16
#define VDIM  64
#define DHD   512
#define HQ    768
#define NPIX  400
#define SPIX  196
#define SA    36
#define SBX   72
#define QTP   24    // Khi/Klo row stride (halves); 12 words -> conflict-free frags
#define VHP   408   // Vh row stride (halves); 204 words -> conflict-free frags
#define QSC   0.3606737602222409f   // 0.25 * log2(e)
#define L2E   1.4426950408889634f

typedef unsigned long long ull;

__device__ __forceinline__ unsigned f2tf(float x) {
    unsigned r; asm("cvt.rna.tf32.f32 %0, %1;" : "=r"(r) : "f"(x)); return r;
}
__device__ __forceinline__ float ex2f(float x) {
    float y; asm("ex2.approx.ftz.f32 %0, %1;" : "=f"(y) : "f"(x)); return y;
}
__device__ __forceinline__ void mma8(float* c, unsigned a0, unsigned a1, unsigned a2, unsigned a3,
                                     unsigned b0, unsigned b1) {
    asm volatile("mma.sync.aligned.m16n8k8.row.col.f32.tf32.tf32.f32 "
        "{%0,%1,%2,%3}, {%4,%5,%6,%7}, {%8,%9}, {%0,%1,%2,%3};"
        : "+f"(c[0]), "+f"(c[1]), "+f"(c[2]), "+f"(c[3])
        : "r"(a0), "r"(a1), "r"(a2), "r"(a3), "r"(b0), "r"(b1));
}
__device__ __forceinline__ void mmah(float* c, unsigned a0, unsigned a1, unsigned a2, unsigned a3,
                                     unsigned b0, unsigned b1) {
    asm volatile("mma.sync.aligned.m16n8k16.row.col.f32.f16.f16.f32 "
        "{%0,%1,%2,%3}, {%4,%5,%6,%7}, {%8,%9}, {%0,%1,%2,%3};"
        : "+f"(c[0]), "+f"(c[1]), "+f"(c[2]), "+f"(c[3])
        : "r"(a0), "r"(a1), "r"(a2), "r"(a3), "r"(b0), "r"(b1));
}
// split float into (hi, lo) f16 pair: x ~= hi + lo to ~2^-22
__device__ __forceinline__ void spl(float x, __half& hi, __half& lo) {
    hi = __float2half(x);
    lo = __float2half(x - __half2float(hi));
}
__device__ __forceinline__ unsigned pack2(__half a, __half b) {
    return (unsigned)__half_as_ushort(a) | ((unsigned)__half_as_ushort(b) << 16);
}

// ---------------- device scratch ----------------
__device__ __align__(16) float g_qkv [NB*HQ*NPIX];
__device__ __align__(16) float g_qdw [NB*128*NPIX];     // pre-scaled by QSC
__device__ __align__(16) float g_tmpb[NHEAD*NPIX*SPIX];
__device__ __align__(16) float g_bias[NHEAD*NPIX*NPIX]; // fragment layout [h][qt][kc][lane][8], *L2E
__device__ __align__(16) float g_ot  [NB*NPIX*DHD];
__device__ __align__(16) float g_y1  [NB*EDIM*NPIX];
__device__ __align__(16) float g_hb  [NB*DHD*NPIX];
__device__ int   g_midx[NPIX*4];
__device__ float g_mw  [NPIX*4];

// ---------------- bicubic taps ----------------
__global__ void k_mtaps() {
    int i = blockIdx.x*blockDim.x + threadIdx.x;
    if (i >= NPIX) return;
    double scale = (double)SPIX / (double)NPIX;
    double src = (i + 0.5)*scale - 0.5;
    double f = floor(src);
    double t = src - f;
    const double a = -0.75;
    for (int j = -1; j <= 2; j++) {
        double xx = fabs((double)j - t);
        double w;
        if (xx <= 1.0)      w = (a+2.0)*xx*xx*xx - (a+3.0)*xx*xx + 1.0;
        else if (xx < 2.0)  w = a*xx*xx*xx - 5.0*a*xx*xx + 8.0*a*xx - 4.0*a;
        else                w = 0.0;
        int idx = (int)f + j;
        idx = min(max(idx, 0), SPIX-1);
        g_midx[i*4 + (j+1)] = idx;
        g_mw  [i*4 + (j+1)] = (float)w;
    }
}

__global__ void k_bias1(const float* __restrict__ ab, const int* __restrict__ idxs) {
    int i = blockIdx.x*blockDim.x + threadIdx.x;
    if (i >= NHEAD*NPIX*SPIX) return;
    int t = i % SPIX;
    int n = (i / SPIX) % NPIX;
    int h = i / (SPIX*NPIX);
    float acc = 0.f;
    #pragma unroll
    for (int k = 0; k < 4; k++) {
        int s = g_midx[n*4+k];
        acc += g_mw[n*4+k] * ab[h*SPIX + idxs[s*SPIX + t]];
    }
    g_tmpb[i] = acc;
}

// bias in m16n8k16 C-fragment order: out[h][qt][kc][lane][j] = L2E * bias(h,q,k)
__global__ void k_bias2() {
    int i = blockIdx.x*blockDim.x + threadIdx.x;
    if (i >= NHEAD*25*25*32*8) return;
    int j    = i & 7;
    int lane = (i >> 3) & 31;
    int kc   = (i >> 8) % 25;
    int qt   = ((i >> 8) / 25) % 25;
    int h    = (i >> 8) / 625;
    int g = lane >> 2, tg = lane & 3;
    int dr = ((j >> 1) & 1) * 8;
    int dc = 2*tg + (j & 1) + ((j >= 4) ? 8 : 0);
    int q = qt*16 + g + dr;
    int k = kc*16 + dc;
    const float* trow = g_tmpb + ((size_t)h*NPIX + q)*SPIX;
    float acc = 0.f;
    #pragma unroll
    for (int kk = 0; kk < 4; kk++)
        acc += g_mw[k*4+kk] * trow[g_midx[k*4+kk]];
    g_bias[i] = acc * L2E;
}

// ---------------- depthwise 3x3 (output pre-scaled by QSC) ----------------
__global__ void k_dwconv(const float* __restrict__ w, const float* __restrict__ s,
                         const float* __restrict__ bia) {
    int i = blockIdx.x*blockDim.x + threadIdx.x;
    if (i >= NB*128*NPIX) return;
    int p = i % NPIX;
    int c = (i / NPIX) % 128;
    int b = i / (128*NPIX);
    int y = p / 20, x = p % 20;
    const float* src = g_qkv + ((size_t)b*HQ + c)*NPIX;
    float acc = 0.f;
    #pragma unroll
    for (int dy = -1; dy <= 1; dy++) {
        int yy = y + dy;
        if (yy < 0 || yy >= 20) continue;
        #pragma unroll
        for (int dx = -1; dx <= 1; dx++) {
            int xx = x + dx;
            if (xx < 0 || xx >= 20) continue;
            acc += w[c*9 + (dy+1)*3 + (dx+1)] * src[yy*20 + xx];
        }
    }
    g_qdw[i] = (acc * s[c] + bia[c]) * QSC;
}

// ---------------- tf32 tensor-core GEMM (unchanged from R7) ----------------
__device__ __forceinline__ void gemm_loadW(const float* __restrict__ W, int Cin,
                                           int oT, int k0, int t, float4* wv) {
    #pragma unroll
    for (int j = 0; j < 4; j++) {
        int qid = t + 256*j;
        int row = qid >> 3, kq = (qid & 7) * 4;
        wv[j] = *(const float4*)&W[(size_t)(oT + row)*Cin + k0 + kq];
    }
}
__device__ __forceinline__ void gemm_loadX(const float* __restrict__ X, int Cin, int b,
                                           int pT, int k0, int t, bool xT, float4* xv) {
    #pragma unroll
    for (int j = 0; j < 2; j++) {
        int qid = t + 256*j;
        float4 v = make_float4(0.f,0.f,0.f,0.f);
        if (!xT) {
            int kx = qid >> 4, pl = (qid & 15) * 4;
            int p  = pT + pl;
            if (p < NPIX) v = *(const float4*)&X[((size_t)b*Cin + k0 + kx)*NPIX + p];
        } else {
            int pl = qid >> 3, kq = (qid & 7) * 4;
            int p  = pT + pl;
            if (p < NPIX) v = *(const float4*)&X[((size_t)b*NPIX + p)*Cin + k0 + kq];
        }
        xv[j] = v;
    }
}
__global__ void __launch_bounds__(256) k_gemm_t(
    const float* __restrict__ X, const float* __restrict__ W,
    const float* __restrict__ sc, const float* __restrict__ bi,
    const float* __restrict__ R, float* __restrict__ Y,
    int O, int Cin, int flags)
{
    __shared__ __align__(16) unsigned Ws[128*SA];
    __shared__ __align__(16) unsigned Xs[32*SBX];
    const int b  = blockIdx.z;
    const int oT = blockIdx.y * 128;
    const int pT = blockIdx.x * 64;
    const int t  = threadIdx.x;
    const int wid = t >> 5, lane = t & 31;
    const int g = lane >> 2, tg = lane & 3;
    const int warpM = wid & 3, warpN = wid >> 2;
    const bool reluIn  = (flags & 1) != 0;
    const bool reluOut = (flags & 2) != 0;
    const bool xT      = (flags & 4) != 0;

    float acc[2][4][4];
    #pragma unroll
    for (int mt = 0; mt < 2; mt++)
        #pragma unroll
        for (int nt = 0; nt < 4; nt++)
            #pragma unroll
            for (int i = 0; i < 4; i++) acc[mt][nt][i] = 0.f;

    const int nchunk = Cin >> 5;
    float4 wv[4], xv[2];
    gemm_loadW(W, Cin, oT, 0, t, wv);
    gemm_loadX(X, Cin, b, pT, 0, t, xT, xv);

    for (int c = 0; c < nchunk; c++) {
        #pragma unroll
        for (int j = 0; j < 4; j++) {
            int qid = t + 256*j;
            int row = qid >> 3, kq = (qid & 7) * 4;
            unsigned* d = &Ws[row*SA + kq];
            d[0] = f2tf(wv[j].x); d[1] = f2tf(wv[j].y);
            d[2] = f2tf(wv[j].z); d[3] = f2tf(wv[j].w);
        }
        #pragma unroll
        for (int j = 0; j < 2; j++) {
            float4 v = xv[j];
            if (reluIn) {
                v.x = fmaxf(v.x,0.f); v.y = fmaxf(v.y,0.f);
                v.z = fmaxf(v.z,0.f); v.w = fmaxf(v.w,0.f);
            }
            int qid = t + 256*j;
            if (!xT) {
                int kx = qid >> 4, pl = (qid & 15) * 4;
                unsigned* d = &Xs[kx*SBX + pl];
                d[0] = f2tf(v.x); d[1] = f2tf(v.y);
                d[2] = f2tf(v.z); d[3] = f2tf(v.w);
            } else {
                int pl = qid >> 3, kq = (qid & 7) * 4;
                Xs[(kq+0)*SBX + pl] = f2tf(v.x);
                Xs[(kq+1)*SBX + pl] = f2tf(v.y);
                Xs[(kq+2)*SBX + pl] = f2tf(v.z);
                Xs[(kq+3)*SBX + pl] = f2tf(v.w);
            }
        }
        __syncthreads();

        if (c + 1 < nchunk) {
            gemm_loadW(W, Cin, oT, (c+1)*32, t, wv);
            gemm_loadX(X, Cin, b, pT, (c+1)*32, t, xT, xv);
        }

        #pragma unroll
        for (int ks = 0; ks < 4; ks++) {
            const int kk = ks * 8;
            unsigned a[2][4], bf[4][2];
            #pragma unroll
            for (int mt = 0; mt < 2; mt++) {
                const unsigned* Ab = &Ws[(warpM*32 + mt*16 + g)*SA + kk + tg];
                a[mt][0] = Ab[0];
                a[mt][1] = Ab[8*SA];
                a[mt][2] = Ab[4];
                a[mt][3] = Ab[8*SA + 4];
            }
            #pragma unroll
            for (int nt = 0; nt < 4; nt++) {
                const unsigned* Bb = &Xs[(kk + tg)*SBX + warpN*32 + nt*8 + g];
                bf[nt][0] = Bb[0];
                bf[nt][1] = Bb[4*SBX];
            }
            #pragma unroll
            for (int mt = 0; mt < 2; mt++)
                #pragma unroll
                for (int nt = 0; nt < 4; nt++)
                    mma8(acc[mt][nt], a[mt][0], a[mt][1], a[mt][2], a[mt][3],
                         bf[nt][0], bf[nt][1]);
        }
        __syncthreads();
    }

    #pragma unroll
    for (int mt = 0; mt < 2; mt++) {
        const int o0 = oT + warpM*32 + mt*16 + g;
        const int o1 = o0 + 8;
        const float s0 = sc[o0], bb0 = bi[o0];
        const float s1 = sc[o1], bb1 = bi[o1];
        #pragma unroll
        for (int nt = 0; nt < 4; nt++) {
            const int p = pT + warpN*32 + nt*8 + 2*tg;
            if (p < NPIX) {
                float2 v0, v1;
                v0.x = acc[mt][nt][0]*s0 + bb0;
                v0.y = acc[mt][nt][1]*s0 + bb0;
                v1.x = acc[mt][nt][2]*s1 + bb1;
                v1.y = acc[mt][nt][3]*s1 + bb1;
                if (reluOut) {
                    v0.x = fmaxf(v0.x,0.f); v0.y = fmaxf(v0.y,0.f);
                    v1.x = fmaxf(v1.x,0.f); v1.y = fmaxf(v1.y,0.f);
                }
                const size_t off0 = ((size_t)b*O + o0)*NPIX + p;
                const size_t off1 = ((size_t)b*O + o1)*NPIX + p;
                if (R) {
                    float2 r0 = *(const float2*)&R[off0];
                    float2 r1 = *(const float2*)&R[off1];
                    v0.x += r0.x; v0.y += r0.y;
                    v1.x += r1.x; v1.y += r1.y;
                }
                *(float2*)&Y[off0] = v0;
                *(float2*)&Y[off1] = v1;
            }
        }
    }
}

// ---------------- tensor-core flash attention, split-f16 ----------------
// One CTA per (b,h), 256 threads (8 warps), 2 CTAs/SM (90.6 KB smem).
// QK: 3-term split-f16 (QhiKhi + QhiKlo + QloKhi) -> score error ~2^-21.
// Q fragments loaded per-tile from GLOBAL fp32 (no smem), split in regs.
// P: 2-term split (registers). V: single f16 (error ~3e-4, acceptable).
__global__ void __launch_bounds__(256, 2) k_attn6() {
    extern __shared__ __half smh[];
    __half* Khi = smh;              // [400][QTP]
    __half* Klo = smh + 9600;       // [400][QTP]
    __half* Vh  = smh + 19200;      // [64][VHP]
    const int bh = blockIdx.x;
    const int b = bh >> 3, h = bh & 7;
    const int tid = threadIdx.x;

    const float* qb = g_qdw + ((size_t)b*128 + h*KDIM)*NPIX;
    const float* kb = g_qkv + ((size_t)b*HQ + 128 + h*KDIM)*NPIX;
    const float* vb = g_qkv + ((size_t)b*HQ + 256 + h*VDIM)*NPIX;

    for (int i = tid; i < KDIM*NPIX; i += 256) {
        int d = i / NPIX, p = i - d*NPIX;
        __half hi, lo; spl(kb[i], hi, lo);
        Khi[p*QTP + d] = hi;
        Klo[p*QTP + d] = lo;
    }
    for (int i = tid; i < VDIM*NPIX; i += 256) {
        int d = i / NPIX, p = i - d*NPIX;
        Vh[d*VHP + p] = __float2half(vb[i]);
    }
    __syncthreads();

    const int w = tid >> 5, lane = tid & 31;
    const int g = lane >> 2, tg = lane & 3;

    for (int tile = w; tile < 25; tile += 8) {
        const int q0 = tile * 16;
        // Q A-fragments from global fp32, split hi/lo in registers.
        // Fragment reg r holds {Q[row][d], Q[row][d+1]}:
        //   qa0: row q0+g,   d=2tg   | qa1: row q0+g+8, d=2tg
        //   qa2: row q0+g,   d=2tg+8 | qa3: row q0+g+8, d=2tg+8
        unsigned qh[4], ql[4];
        {
            const int r0 = q0 + g, r1 = q0 + g + 8;
            const int d0 = 2*tg, d1 = 2*tg + 8;
            float q00a = qb[(d0  )*NPIX + r0], q00b = qb[(d0+1)*NPIX + r0];
            float q10a = qb[(d0  )*NPIX + r1], q10b = qb[(d0+1)*NPIX + r1];
            float q01a = qb[(d1  )*NPIX + r0], q01b = qb[(d1+1)*NPIX + r0];
            float q11a = qb[(d1  )*NPIX + r1], q11b = qb[(d1+1)*NPIX + r1];
            __half ha, la, hb2, lb2;
            spl(q00a, ha, la); spl(q00b, hb2, lb2);
            qh[0] = pack2(ha, hb2); ql[0] = pack2(la, lb2);
            spl(q10a, ha, la); spl(q10b, hb2, lb2);
            qh[1] = pack2(ha, hb2); ql[1] = pack2(la, lb2);
            spl(q01a, ha, la); spl(q01b, hb2, lb2);
            qh[2] = pack2(ha, hb2); ql[2] = pack2(la, lb2);
            spl(q11a, ha, la); spl(q11b, hb2, lb2);
            qh[3] = pack2(ha, hb2); ql[3] = pack2(la, lb2);
        }

        float o[8][4];
        #pragma unroll
        for (int dt = 0; dt < 8; dt++)
            #pragma unroll
            for (int i = 0; i < 4; i++) o[dt][i] = 0.f;
        float m_g = -1e30f, m_h = -1e30f, den_g = 0.f, den_h = 0.f;

        const float* bfrag = &g_bias[((((size_t)h*25 + tile)*25)*32 + lane)*8];

        for (int kc = 0; kc < 25; kc++) {
            const int k0 = kc * 16;
            // ---- QK: 3-term split, 2 key tiles ----
            float s0[4] = {0.f,0.f,0.f,0.f};
            float s1[4] = {0.f,0.f,0.f,0.f};
            {
                unsigned b0h = *(const unsigned*)&Khi[(k0+g)*QTP + 2*tg];
                unsigned b1h = *(const unsigned*)&Khi[(k0+g)*QTP + 2*tg + 8];
                unsigned b0l = *(const unsigned*)&Klo[(k0+g)*QTP + 2*tg];
                unsigned b1l = *(const unsigned*)&Klo[(k0+g)*QTP + 2*tg + 8];
                mmah(s0, qh[0], qh[1], qh[2], qh[3], b0h, b1h);
                mmah(s0, qh[0], qh[1], qh[2], qh[3], b0l, b1l);
                mmah(s0, ql[0], ql[1], ql[2], ql[3], b0h, b1h);
                unsigned c0h = *(const unsigned*)&Khi[(k0+8+g)*QTP + 2*tg];
                unsigned c1h = *(const unsigned*)&Khi[(k0+8+g)*QTP + 2*tg + 8];
                unsigned c0l = *(const unsigned*)&Klo[(k0+8+g)*QTP + 2*tg];
                unsigned c1l = *(const unsigned*)&Klo[(k0+8+g)*QTP + 2*tg + 8];
                mmah(s1, qh[0], qh[1], qh[2], qh[3], c0h, c1h);
                mmah(s1, qh[0], qh[1], qh[2], qh[3], c0l, c1l);
                mmah(s1, ql[0], ql[1], ql[2], ql[3], c0h, c1h);
            }
            // ---- bias add (fragment layout; kc stride = 32*8 = 256 floats) ----
            const float4 bv0 = *(const float4*)(bfrag + (size_t)kc*256);
            const float4 bv1 = *(const float4*)(bfrag + (size_t)kc*256 + 4);
            s0[0] += bv0.x; s0[1] += bv0.y; s0[2] += bv0.z; s0[3] += bv0.w;
            s1[0] += bv1.x; s1[1] += bv1.y; s1[2] += bv1.z; s1[3] += bv1.w;
            // ---- chunk row maxes (rows g and g+8) ----
            float cmg = fmaxf(fmaxf(s0[0], s0[1]), fmaxf(s1[0], s1[1]));
            float cmh = fmaxf(fmaxf(s0[2], s0[3]), fmaxf(s1[2], s1[3]));
            cmg = fmaxf(cmg, __shfl_xor_sync(0xffffffffu, cmg, 1));
            cmg = fmaxf(cmg, __shfl_xor_sync(0xffffffffu, cmg, 2));
            cmh = fmaxf(cmh, __shfl_xor_sync(0xffffffffu, cmh, 1));
            cmh = fmaxf(cmh, __shfl_xor_sync(0xffffffffu, cmh, 2));
            // ---- online rescale (warp-uniform predicate; rare) ----
            if (__any_sync(0xffffffffu, (cmg > m_g) || (cmh > m_h))) {
                float nm_g = fmaxf(m_g, cmg), nm_h = fmaxf(m_h, cmh);
                float rg = ex2f(m_g - nm_g), rh = ex2f(m_h - nm_h);
                den_g *= rg; den_h *= rh;
                #pragma unroll
                for (int dt = 0; dt < 8; dt++) {
                    o[dt][0] *= rg; o[dt][1] *= rg;
                    o[dt][2] *= rh; o[dt][3] *= rh;
                }
                m_g = nm_g; m_h = nm_h;
            }
            // ---- P = exp2(S - m); split P; denominators ----
            float p00 = ex2f(s0[0] - m_g), p01 = ex2f(s0[1] - m_g);
            float p02 = ex2f(s0[2] - m_h), p03 = ex2f(s0[3] - m_h);
            float p10 = ex2f(s1[0] - m_g), p11 = ex2f(s1[1] - m_g);
            float p12 = ex2f(s1[2] - m_h), p13 = ex2f(s1[3] - m_h);
            den_g += (p00 + p01) + (p10 + p11);
            den_h += (p02 + p03) + (p12 + p13);
            unsigned ph[4], pl[4];
            {
                __half ha, la, hb2, lb2;
                spl(p00, ha, la); spl(p01, hb2, lb2);
                ph[0] = pack2(ha, hb2); pl[0] = pack2(la, lb2);
                spl(p02, ha, la); spl(p03, hb2, lb2);
                ph[1] = pack2(ha, hb2); pl[1] = pack2(la, lb2);
                spl(p10, ha, la); spl(p11, hb2, lb2);
                ph[2] = pack2(ha, hb2); pl[2] = pack2(la, lb2);
                spl(p12, ha, la); spl(p13, hb2, lb2);
                ph[3] = pack2(ha, hb2); pl[3] = pack2(la, lb2);
            }
            // ---- PV: 8 d-tiles, 2-term P split ----
            #pragma unroll
            for (int dt = 0; dt < 8; dt++) {
                unsigned vb0 = *(const unsigned*)&Vh[(dt*8+g)*VHP + k0 + 2*tg];
                unsigned vb1 = *(const unsigned*)&Vh[(dt*8+g)*VHP + k0 + 2*tg + 8];
                mmah(o[dt], ph[0], ph[1], ph[2], ph[3], vb0, vb1);
                mmah(o[dt], pl[0], pl[1], pl[2], pl[3], vb0, vb1);
            }
        }
        // ---- epilogue: quad-reduce denominators, normalize, store ----
        den_g += __shfl_xor_sync(0xffffffffu, den_g, 1);
        den_g += __shfl_xor_sync(0xffffffffu, den_g, 2);
        den_h += __shfl_xor_sync(0xffffffffu, den_h, 1);
        den_h += __shfl_xor_sync(0xffffffffu, den_h, 2);
        const float ig = 1.f / den_g, ih = 1.f / den_h;
        float* org = &g_ot[((size_t)b*NPIX + q0 + g)*DHD + h*VDIM];
        float* orh = &g_ot[((size_t)b*NPIX + q0 + g + 8)*DHD + h*VDIM];
        #pragma unroll
        for (int dt = 0; dt < 8; dt++) {
            float2 v0, v1;
            v0.x = o[dt][0] * ig; v0.y = o[dt][1] * ig;
            v1.x = o[dt][2] * ih; v1.y = o[dt][3] * ih;
            *(float2*)&org[dt*8 + 2*tg] = v0;
            *(float2*)&orh[dt*8 + 2*tg] = v1;
        }
    }
}

// ---------------- launch ----------------
extern "C" void kernel_launch(void* const* d_in, const int* in_sizes, int n_in,
                              void* d_out, int out_size) {
    const float* x      = (const float*)d_in[0];
    const float* qkv_w  = (const float*)d_in[1];
    const float* qkv_s  = (const float*)d_in[2];
    const float* qkv_b  = (const float*)d_in[3];
    const float* dw_w   = (const float*)d_in[4];
    const float* dw_s   = (const float*)d_in[5];
    const float* dw_b   = (const float*)d_in[6];
    const float* proj_w = (const float*)d_in[7];
    const float* proj_s = (const float*)d_in[8];
    const float* proj_b = (const float*)d_in[9];
    const float* ab     = (const float*)d_in[10];
    const float* pw1_w  = (const float*)d_in[11];
    const float* pw1_s  = (const float*)d_in[12];
    const float* pw1_b  = (const float*)d_in[13];
    const float* pw2_w  = (const float*)d_in[14];
    const float* pw2_s  = (const float*)d_in[15];
    const float* pw2_b  = (const float*)d_in[16];
    const int*   idxs   = (const int*)d_in[17];

    float *p_qkv, *p_ot, *p_y1, *p_hb;
    cudaGetSymbolAddress((void**)&p_qkv, g_qkv);
    cudaGetSymbolAddress((void**)&p_ot,  g_ot);
    cudaGetSymbolAddress((void**)&p_y1,  g_y1);
    cudaGetSymbolAddress((void**)&p_hb,  g_hb);

    // bias pipeline
    k_mtaps<<<1, 512>>>();
    k_bias1<<<(NHEAD*NPIX*SPIX + 255)/256, 256>>>(ab, idxs);
    k_bias2<<<(NHEAD*25*25*32*8 + 255)/256, 256>>>();

    // qkv conv1x1 (tf32 mma)
    k_gemm_t<<<dim3(7, HQ/128, NB), 256>>>(x, qkv_w, qkv_s, qkv_b, nullptr, p_qkv, HQ, EDIM, 0);
    // depthwise 3x3 on q (pre-scaled for log2-domain softmax)
    k_dwconv<<<(NB*128*NPIX + 255)/256, 256>>>(dw_w, dw_s, dw_b);

    // tensor-core flash attention (split-f16)
    const int smem = (9600 + 9600 + VDIM*VHP) * 2;  // 90624 B
    cudaFuncSetAttribute(k_attn6, cudaFuncAttributeMaxDynamicSharedMemorySize, smem);
    k_attn6<<<NB*NHEAD, 256, smem>>>();

    // proj (relu-in, X transposed, residual x) -> y1
    k_gemm_t<<<dim3(7, EDIM/128, NB), 256>>>(p_ot, proj_w, proj_s, proj_b, x, p_y1, EDIM, DHD, 1|4);
    // pw1 (relu-out) -> h
    k_gemm_t<<<dim3(7, DHD/128, NB), 256>>>(p_y1, pw1_w, pw1_s, pw1_b, nullptr, p_hb, DHD, EDIM, 2);
    // pw2 (residual y1) -> out
    k_gemm_t<<<dim3(7, EDIM/128, NB), 256>>>(p_hb, pw2_w, pw2_s, pw2_b, p_y1, (float*)d_out, EDIM, DHD, 0);
}